// round 6
// baseline (speedup 1.0000x reference)
#include <cuda_runtime.h>
#include <math.h>

// ---------------- config ----------------
#define NB      16      // CTAs in the persistent grid (one wave, co-resident)
#define NT      256     // threads per CTA
#define TSTEPS  800     // N_ENC * COND_REPEAT
#define NL      16      // layers
// B=4, R=128, S=128, CC=64, CLASSES=256

// ---------------- device scratch (allocation-free) ----------------
__device__ float g_queue[261120];            // dilation rings: sum(dil)=510, *B*R
__device__ float g_condz[16*4*4*256];        // [l][e][b][2R]  (Wcond@c + bc)
__device__ float g_condtop[4*4*128];         // [e][b][S]      (Wcond_top@c + bfc)
__device__ float g_bskip[128];               // bskip0 + sum_l bskip_l
__device__ float g_Wskip0T[128*128];         // [r][s]
__device__ float g_WskipT[16*128*128];       // [l][r][s]
__device__ float g_hbuf[512];                // [b][R]
__device__ float g_resbuf[512];              // [b][R]
__device__ float g_skipP[NB*512];            // [g][b][S] partial skip
__device__ float g_relu[512];                // [b][S]
__device__ float g_sv[512];                  // [b][S]
__device__ float g_log[1024];                // [b][CLASSES]
__device__ int   g_sample[4];
__device__ unsigned g_bar_count;             // self-resetting barrier state
__device__ unsigned g_bar_gen;

__constant__ int c_dil[NL]  = {1,2,4,8,16,32,64,128,1,2,4,8,16,32,64,128};
__constant__ int c_qoff[NL] = {0,512,1536,3584,7680,15872,32256,65024,
                               130560,131072,132096,134144,138240,146432,162816,195584};

// ---------------- grid barrier (16 co-resident CTAs, self-resetting) ----------------
__device__ __forceinline__ void grid_sync() {
    __syncthreads();
    if (threadIdx.x == 0) {
        __threadfence();
        unsigned gen = *(volatile unsigned*)&g_bar_gen;
        if (atomicAdd(&g_bar_count, 1u) == NB - 1) {
            atomicExch(&g_bar_count, 0u);
            __threadfence();
            atomicAdd(&g_bar_gen, 1u);
        } else {
            while (*(volatile unsigned*)&g_bar_gen == gen) { }
        }
        __threadfence();
    }
    __syncthreads();
}

// ---------------- prep kernels (recomputed every launch; deterministic) ----------------
__global__ void prep_condz(const float* __restrict__ enc, const float* __restrict__ Wcond,
                           const float* __restrict__ bc) {
    int idx = blockIdx.x * blockDim.x + threadIdx.x;   // 65536
    int row = idx & 255, b = (idx >> 8) & 3, e = (idx >> 10) & 3, l = idx >> 12;
    float v = bc[l*256 + row];
    const float* w = Wcond + (l*256 + row)*64;
    #pragma unroll 8
    for (int c = 0; c < 64; ++c) v = fmaf(w[c], enc[b*256 + c*4 + e], v);
    g_condz[((l*4 + e)*4 + b)*256 + row] = v;
}

__global__ void prep_condtop(const float* __restrict__ enc, const float* __restrict__ Wct,
                             const float* __restrict__ bfc) {
    int idx = blockIdx.x * blockDim.x + threadIdx.x;   // 2048
    int s = idx & 127, b = (idx >> 7) & 3, e = idx >> 9;
    float v = bfc[s];
    #pragma unroll 8
    for (int c = 0; c < 64; ++c) v = fmaf(Wct[s*64 + c], enc[b*256 + c*4 + e], v);
    g_condtop[(e*4 + b)*128 + s] = v;
}

__global__ void prep_bskip(const float* __restrict__ bskip0, const float* __restrict__ bskip_l) {
    int s = threadIdx.x;  // 128
    float v = bskip0[s];
    #pragma unroll
    for (int l = 0; l < NL; ++l) v += bskip_l[l*128 + s];
    g_bskip[s] = v;
}

__global__ void prep_t0(const float* __restrict__ Wskip0) {
    int i = blockIdx.x * blockDim.x + threadIdx.x;     // 16384
    int r = i >> 7, s = i & 127;
    g_Wskip0T[r*128 + s] = Wskip0[s*128 + r];
}

__global__ void prep_t1(const float* __restrict__ Wskip_l) {
    int i = blockIdx.x * blockDim.x + threadIdx.x;     // 262144
    int l = i >> 14, rem = i & 16383, r = rem >> 7, s = rem & 127;
    g_WskipT[(l*128 + r)*128 + s] = Wskip_l[(l*128 + s)*128 + r];
}

// ---------------- main persistent kernel ----------------
__global__ void __launch_bounds__(NT, 1)
wnet_main(const float* __restrict__ Wf,   const float* __restrict__ bf,
          const float* __restrict__ Wc,   const float* __restrict__ Wres,
          const float* __restrict__ bres, const float* __restrict__ Wfc,
          const float* __restrict__ Wlog, const float* __restrict__ blog,
          float* __restrict__ out)
{
    const int g   = blockIdx.x;
    const int tid = threadIdx.x;

    __shared__ float s_res[4][132];   // full residual, replicated per CTA
    __shared__ float s_q0[4][132];    // q0 / full-h / relu-skip / s  (reused)
    __shared__ float s_z[16][4];      // CTA's z rows (8 gate + 8 out)
    __shared__ float s_h[8][4];       // CTA's h slice
    __shared__ float s_x[4], s_xp[4];

    if (tid < 4) { s_x[tid] = 128.0f/127.5f - 1.0f; s_xp[tid] = 0.0f; }

    // thread roles
    const int my_s  = tid & 127, my_b = tid >> 7;            // skip accum: (s, b) & (s, b+2)
    const int dn4   = tid >> 2,  t4   = tid & 3;             // 64 dots x 4 threads
    const int rowA  = dn4 >> 2,  bA   = dn4 & 3;             // rowA in [0,16)
    const int zrow  = (rowA < 8) ? (g*8 + rowA) : (128 + g*8 + rowA - 8);
    const int dn8   = tid >> 3,  t8   = tid & 7;             // 32 dots x 8 threads
    const int rB    = dn8 >> 2,  bB   = dn8 & 3;             // rB in [0,8)

    for (int t = 0; t < TSTEPS; ++t) {
        const int e = t / 200;
        __syncthreads();  // s_x/s_xp visible

        // first causal conv: res0 = xp*W0 + x*W1 + b   (replicated full)
        for (int idx = tid; idx < 512; idx += NT) {
            int b = idx >> 7, k = idx & 127;
            s_res[b][k] = fmaf(s_xp[b], Wf[2*k], fmaf(s_x[b], Wf[2*k+1], bf[k]));
        }
        __syncthreads();

        // skip init: Wskip0 partial over this CTA's 8 input columns
        float sa0 = 0.f, sa1 = 0.f;
        #pragma unroll
        for (int j = 0; j < 8; ++j) {
            float w = g_Wskip0T[(g*8 + j)*128 + my_s];
            sa0 = fmaf(w, s_res[my_b    ][g*8 + j], sa0);
            sa1 = fmaf(w, s_res[my_b + 2][g*8 + j], sa1);
        }

        #pragma unroll 1
        for (int l = 0; l < NL; ++l) {
            const int d   = c_dil[l];
            const int pos = t & (d - 1);
            float* qbase  = g_queue + c_qoff[l] + pos*512;

            // load q0 (oldest ring entry; zeros before warm-up) — cross-SM data: bypass L1
            for (int idx = tid; idx < 512; idx += NT)
                s_q0[idx >> 7][idx & 127] = (t >= d) ? __ldcg(qbase + idx) : 0.f;
            __syncthreads();

            // Phase A: z slice = Wc0.q0 + Wc1.res + condz
            {
                const float2* wp = reinterpret_cast<const float2*>(Wc) + (l*256 + zrow)*128;
                float acc = 0.f;
                #pragma unroll
                for (int i = 0; i < 32; ++i) {
                    int k = t4 + 4*i;
                    float2 w = wp[k];
                    acc = fmaf(w.x, s_q0[bA][k], acc);
                    acc = fmaf(w.y, s_res[bA][k], acc);
                }
                acc += __shfl_down_sync(0xffffffffu, acc, 2);
                acc += __shfl_down_sync(0xffffffffu, acc, 1);
                if (t4 == 0)
                    s_z[rowA][bA] = acc + g_condz[((l*4 + e)*4 + bA)*256 + zrow];
            }
            __syncthreads();

            // gated activation (8 channels x 4 batch)
            if (tid < 32) {
                int j = tid >> 2, b = tid & 3;
                float gate = s_z[j][b], ov = s_z[j + 8][b];
                float h = tanhf(ov) / (1.f + expf(-gate));
                s_h[j][b] = h;
                __stcg(&g_hbuf[b*128 + g*8 + j], h);
            }
            __syncthreads();

            // skip accumulate (off critical path, local registers)
            #pragma unroll
            for (int j = 0; j < 8; ++j) {
                float w = g_WskipT[(l*128 + g*8 + j)*128 + my_s];
                sa0 = fmaf(w, s_h[j][my_b    ], sa0);
                sa1 = fmaf(w, s_h[j][my_b + 2], sa1);
            }

            grid_sync();   // barrier 1: h fully published

            // load full h (reuse s_q0)
            for (int idx = tid; idx < 512; idx += NT)
                s_q0[idx >> 7][idx & 127] = __ldcg(&g_hbuf[idx]);
            __syncthreads();

            // Phase B: res slice update
            {
                const int rg = g*8 + rB;
                const float* wr = Wres + (l*128 + rg)*128;
                float acc = 0.f;
                #pragma unroll
                for (int i = 0; i < 16; ++i) {
                    int k = t8 + 8*i;
                    acc = fmaf(wr[k], s_q0[bB][k], acc);
                }
                acc += __shfl_down_sync(0xffffffffu, acc, 4);
                acc += __shfl_down_sync(0xffffffffu, acc, 2);
                acc += __shfl_down_sync(0xffffffffu, acc, 1);
                if (t8 == 0)
                    __stcg(&g_resbuf[bB*128 + rg], s_res[bB][rg] + acc + bres[l*128 + rg]);
            }

            // push old res slice into the ring (all reads of this slot happened pre-barrier-1)
            if (tid < 32) {
                int b = tid >> 3, j = tid & 7;
                __stcg(qbase + b*128 + g*8 + j, s_res[b][g*8 + j]);
            }

            grid_sync();   // barrier 2: res fully published

            for (int idx = tid; idx < 512; idx += NT)
                s_res[idx >> 7][idx & 127] = __ldcg(&g_resbuf[idx]);
            // next layer's q0-load __syncthreads orders these writes
        }

        // ---- tail: skip reduce -> fc -> logits -> argmax ----
        __stcg(&g_skipP[(g*4 + my_b    )*128 + my_s], sa0);
        __stcg(&g_skipP[(g*4 + my_b + 2)*128 + my_s], sa1);
        grid_sync();

        if (tid < 32) {   // reduce own 8 skip outputs, relu
            int so = g*8 + (tid >> 2), b = tid & 3;
            float acc = g_bskip[so];
            #pragma unroll
            for (int gg = 0; gg < NB; ++gg)
                acc += __ldcg(&g_skipP[(gg*4 + b)*128 + so]);
            __stcg(&g_relu[b*128 + so], fmaxf(acc, 0.f));
        }
        grid_sync();

        for (int idx = tid; idx < 512; idx += NT)
            s_q0[idx >> 7][idx & 127] = __ldcg(&g_relu[idx]);
        __syncthreads();
        {   // fc (bfc folded into condtop), relu
            const int so = g*8 + rB;
            const float* wf = Wfc + so*128;
            float acc = 0.f;
            #pragma unroll
            for (int i = 0; i < 16; ++i) { int k = t8 + 8*i; acc = fmaf(wf[k], s_q0[bB][k], acc); }
            acc += __shfl_down_sync(0xffffffffu, acc, 4);
            acc += __shfl_down_sync(0xffffffffu, acc, 2);
            acc += __shfl_down_sync(0xffffffffu, acc, 1);
            if (t8 == 0) {
                float v = acc + g_condtop[(e*4 + bB)*128 + so];
                __stcg(&g_sv[bB*128 + so], fmaxf(v, 0.f));
            }
        }
        grid_sync();

        for (int idx = tid; idx < 512; idx += NT)
            s_q0[idx >> 7][idx & 127] = __ldcg(&g_sv[idx]);
        __syncthreads();
        {   // logits: 16 classes per CTA
            const int cls = g*16 + rowA;
            const float* wl = Wlog + cls*128;
            float acc = 0.f;
            #pragma unroll
            for (int i = 0; i < 32; ++i) { int k = t4 + 4*i; acc = fmaf(wl[k], s_q0[bA][k], acc); }
            acc += __shfl_down_sync(0xffffffffu, acc, 2);
            acc += __shfl_down_sync(0xffffffffu, acc, 1);
            if (t4 == 0) {
                float lv = acc + blog[cls];
                out[(bA*256 + cls)*TSTEPS + t] = lv;       // final output
                __stcg(&g_log[bA*256 + cls], lv);
            }
        }
        grid_sync();

        // argmax (first-occurrence semantics, matches jnp.argmax)
        if (g == 0 && tid < 128) {
            int b = tid >> 5, lane = tid & 31;
            float best = -3.4e38f; int bi = 0;
            #pragma unroll
            for (int m = 0; m < 8; ++m) {
                int c = lane*8 + m;
                float v = __ldcg(&g_log[b*256 + c]);
                if (v > best) { best = v; bi = c; }
            }
            #pragma unroll
            for (int off = 16; off > 0; off >>= 1) {
                float ob = __shfl_down_sync(0xffffffffu, best, off);
                int   oi = __shfl_down_sync(0xffffffffu, bi,   off);
                if (ob > best) { best = ob; bi = oi; }   // higher lane = higher idx: strict > keeps first
            }
            if (lane == 0) { int* ps = &g_sample[b]; __stcg(ps, bi); }
        }
        grid_sync();

        if (tid < 4) {
            int smp = __ldcg(&g_sample[tid]);
            s_xp[tid] = s_x[tid];
            s_x[tid]  = (float)smp / 127.5f - 1.0f;
        }
    }
}

// ---------------- launch ----------------
extern "C" void kernel_launch(void* const* d_in, const int* in_sizes, int n_in,
                              void* d_out, int out_size) {
    const float* enc       = (const float*)d_in[0];
    const float* Wf        = (const float*)d_in[1];
    const float* bf        = (const float*)d_in[2];
    const float* Wc        = (const float*)d_in[3];
    const float* bc        = (const float*)d_in[4];
    const float* Wcond     = (const float*)d_in[5];
    const float* Wres      = (const float*)d_in[6];
    const float* bres      = (const float*)d_in[7];
    const float* Wskip_l   = (const float*)d_in[8];
    const float* bskip_l   = (const float*)d_in[9];
    const float* Wskip0    = (const float*)d_in[10];
    const float* bskip0    = (const float*)d_in[11];
    const float* Wcond_top = (const float*)d_in[12];
    const float* Wfc       = (const float*)d_in[13];
    const float* bfc       = (const float*)d_in[14];
    const float* Wlog      = (const float*)d_in[15];
    const float* blog      = (const float*)d_in[16];
    float* out = (float*)d_out;

    prep_condz  <<<256, 256>>>(enc, Wcond, bc);
    prep_condtop<<<8,   256>>>(enc, Wcond_top, bfc);
    prep_bskip  <<<1,   128>>>(bskip0, bskip_l);
    prep_t0     <<<64,  256>>>(Wskip0);
    prep_t1     <<<1024,256>>>(Wskip_l);
    wnet_main   <<<NB,  NT >>>(Wf, bf, Wc, Wres, bres, Wfc, Wlog, blog, out);
}

// round 10
// speedup vs baseline: 1.0275x; 1.0275x over previous
#include <cuda_runtime.h>
#include <math.h>

// ---------------- config ----------------
#define NB      16      // CTAs in the persistent grid (one wave, co-resident)
#define NT      256     // threads per CTA
#define TSTEPS  800     // N_ENC * COND_REPEAT
#define NL      16      // layers
// B=4, R=128, S=128, CC=64, CLASSES=256

// ---------------- device scratch (allocation-free) ----------------
__device__ float g_queue[261120];            // dilation rings: sum(dil)=510, *B*R
__device__ float g_condz[16*4*4*256];        // [l][e][b][2R]  (Wcond@c + bc)
__device__ float g_condtop[4*4*128];         // [e][b][S]      (Wcond_top@c + bfc)
__device__ float g_bskip[128];               // bskip0 + sum_l bskip_l
__device__ float g_Wskip0T[128*128];         // [r][s]
__device__ float g_WskipT[16*128*128];       // [l][r][s]
__device__ float g_hbuf[512];                // [b][R]
__device__ float g_resbuf[512];              // [b][R]
__device__ float g_skipP[NB*512];            // [g][b][S] partial skip
__device__ float g_relu[512];                // [b][S]
__device__ float g_sv[512];                  // [b][S]
__device__ float g_log[1024];                // [b][CLASSES]
__device__ int   g_sample[4];
__device__ unsigned g_bar_count;             // self-resetting barrier state
__device__ unsigned g_bar_gen;

__constant__ int c_dil[NL]  = {1,2,4,8,16,32,64,128,1,2,4,8,16,32,64,128};
__constant__ int c_qoff[NL] = {0,512,1536,3584,7680,15872,32256,65024,
                               130560,131072,132096,134144,138240,146432,162816,195584};

// ---------------- grid barrier (16 co-resident CTAs, self-resetting) ----------------
__device__ __forceinline__ void grid_sync() {
    __syncthreads();
    if (threadIdx.x == 0) {
        __threadfence();
        unsigned gen = *(volatile unsigned*)&g_bar_gen;
        if (atomicAdd(&g_bar_count, 1u) == NB - 1) {
            atomicExch(&g_bar_count, 0u);
            __threadfence();
            atomicAdd(&g_bar_gen, 1u);
        } else {
            while (*(volatile unsigned*)&g_bar_gen == gen) { }
        }
        __threadfence();
    }
    __syncthreads();
}

// ---------------- prep kernels (recomputed every launch; deterministic) ----------------
__global__ void prep_condz(const float* __restrict__ enc, const float* __restrict__ Wcond,
                           const float* __restrict__ bc) {
    int idx = blockIdx.x * blockDim.x + threadIdx.x;   // 65536
    int row = idx & 255, b = (idx >> 8) & 3, e = (idx >> 10) & 3, l = idx >> 12;
    float v = bc[l*256 + row];
    const float* w = Wcond + (l*256 + row)*64;
    #pragma unroll 8
    for (int c = 0; c < 64; ++c) v = fmaf(w[c], enc[b*256 + c*4 + e], v);
    g_condz[((l*4 + e)*4 + b)*256 + row] = v;
}

__global__ void prep_condtop(const float* __restrict__ enc, const float* __restrict__ Wct,
                             const float* __restrict__ bfc) {
    int idx = blockIdx.x * blockDim.x + threadIdx.x;   // 2048
    int s = idx & 127, b = (idx >> 7) & 3, e = idx >> 9;
    float v = bfc[s];
    #pragma unroll 8
    for (int c = 0; c < 64; ++c) v = fmaf(Wct[s*64 + c], enc[b*256 + c*4 + e], v);
    g_condtop[(e*4 + b)*128 + s] = v;
}

__global__ void prep_bskip(const float* __restrict__ bskip0, const float* __restrict__ bskip_l) {
    int s = threadIdx.x;  // 128
    float v = bskip0[s];
    #pragma unroll
    for (int l = 0; l < NL; ++l) v += bskip_l[l*128 + s];
    g_bskip[s] = v;
}

__global__ void prep_t0(const float* __restrict__ Wskip0) {
    int i = blockIdx.x * blockDim.x + threadIdx.x;     // 16384
    int r = i >> 7, s = i & 127;
    g_Wskip0T[r*128 + s] = Wskip0[s*128 + r];
}

__global__ void prep_t1(const float* __restrict__ Wskip_l) {
    int i = blockIdx.x * blockDim.x + threadIdx.x;     // 262144
    int l = i >> 14, rem = i & 16383, r = rem >> 7, s = rem & 127;
    g_WskipT[(l*128 + r)*128 + s] = Wskip_l[(l*128 + s)*128 + r];
}

// ---------------- main persistent kernel ----------------
__global__ void __launch_bounds__(NT, 1)
wnet_main(const float* __restrict__ Wf,   const float* __restrict__ bf,
          const float* __restrict__ Wc,   const float* __restrict__ Wres,
          const float* __restrict__ bres, const float* __restrict__ Wfc,
          const float* __restrict__ Wlog, const float* __restrict__ blog,
          float* __restrict__ out)
{
    const int g   = blockIdx.x;
    const int tid = threadIdx.x;

    __shared__ float s_res[4][132];   // full residual, replicated per CTA
    __shared__ float s_q0[4][132];    // q0 / full-h / relu-skip / s  (reused)
    __shared__ float s_z[16][4];      // CTA's z rows (8 gate + 8 out)
    __shared__ float s_h[8][4];       // CTA's h slice
    __shared__ float s_x[4], s_xp[4];

    if (tid < 4) { s_x[tid] = 128.0f/127.5f - 1.0f; s_xp[tid] = 0.0f; }

    // thread roles
    const int my_s  = tid & 127, my_b = tid >> 7;            // skip accum: (s, b) & (s, b+2)
    const int dn4   = tid >> 2,  t4   = tid & 3;             // 64 dots x 4 threads
    const int rowA  = dn4 >> 2,  bA   = dn4 & 3;             // rowA in [0,16)
    const int zrow  = (rowA < 8) ? (g*8 + rowA) : (128 + g*8 + rowA - 8);
    const int dn8   = tid >> 3,  t8   = tid & 7;             // 32 dots x 8 threads
    const int rB    = dn8 >> 2,  bB   = dn8 & 3;             // rB in [0,8)

    for (int t = 0; t < TSTEPS; ++t) {
        const int e = t / 200;
        __syncthreads();  // s_x/s_xp visible

        // first causal conv: res0 = xp*W0 + x*W1 + b   (replicated full)
        for (int idx = tid; idx < 512; idx += NT) {
            int b = idx >> 7, k = idx & 127;
            s_res[b][k] = fmaf(s_xp[b], Wf[2*k], fmaf(s_x[b], Wf[2*k+1], bf[k]));
        }
        __syncthreads();

        // skip init: Wskip0 partial over this CTA's 8 input columns
        float sa0 = 0.f, sa1 = 0.f;
        #pragma unroll
        for (int j = 0; j < 8; ++j) {
            float w = g_Wskip0T[(g*8 + j)*128 + my_s];
            sa0 = fmaf(w, s_res[my_b    ][g*8 + j], sa0);
            sa1 = fmaf(w, s_res[my_b + 2][g*8 + j], sa1);
        }

        #pragma unroll 1
        for (int l = 0; l < NL; ++l) {
            const int d   = c_dil[l];
            const int pos = t & (d - 1);
            float* qbase  = g_queue + c_qoff[l] + pos*512;

            // load q0 (oldest ring entry; zeros before warm-up) — cross-SM data: bypass L1
            for (int idx = tid; idx < 512; idx += NT)
                s_q0[idx >> 7][idx & 127] = (t >= d) ? __ldcg(qbase + idx) : 0.f;
            __syncthreads();

            // Phase A: z slice = Wc0.q0 + Wc1.res + condz
            {
                const float2* wp = reinterpret_cast<const float2*>(Wc) + (l*256 + zrow)*128;
                float acc = 0.f;
                #pragma unroll
                for (int i = 0; i < 32; ++i) {
                    int k = t4 + 4*i;
                    float2 w = wp[k];
                    acc = fmaf(w.x, s_q0[bA][k], acc);
                    acc = fmaf(w.y, s_res[bA][k], acc);
                }
                acc += __shfl_down_sync(0xffffffffu, acc, 2);
                acc += __shfl_down_sync(0xffffffffu, acc, 1);
                if (t4 == 0)
                    s_z[rowA][bA] = acc + g_condz[((l*4 + e)*4 + bA)*256 + zrow];
            }
            __syncthreads();

            // gated activation (8 channels x 4 batch)
            if (tid < 32) {
                int j = tid >> 2, b = tid & 3;
                float gate = s_z[j][b], ov = s_z[j + 8][b];
                float h = tanhf(ov) / (1.f + expf(-gate));
                s_h[j][b] = h;
                __stcg(&g_hbuf[b*128 + g*8 + j], h);
            }
            __syncthreads();

            // skip accumulate (off critical path, local registers)
            #pragma unroll
            for (int j = 0; j < 8; ++j) {
                float w = g_WskipT[(l*128 + g*8 + j)*128 + my_s];
                sa0 = fmaf(w, s_h[j][my_b    ], sa0);
                sa1 = fmaf(w, s_h[j][my_b + 2], sa1);
            }

            grid_sync();   // barrier 1: h fully published

            // load full h (reuse s_q0)
            for (int idx = tid; idx < 512; idx += NT)
                s_q0[idx >> 7][idx & 127] = __ldcg(&g_hbuf[idx]);
            __syncthreads();

            // Phase B: res slice update
            {
                const int rg = g*8 + rB;
                const float* wr = Wres + (l*128 + rg)*128;
                float acc = 0.f;
                #pragma unroll
                for (int i = 0; i < 16; ++i) {
                    int k = t8 + 8*i;
                    acc = fmaf(wr[k], s_q0[bB][k], acc);
                }
                acc += __shfl_down_sync(0xffffffffu, acc, 4);
                acc += __shfl_down_sync(0xffffffffu, acc, 2);
                acc += __shfl_down_sync(0xffffffffu, acc, 1);
                if (t8 == 0)
                    __stcg(&g_resbuf[bB*128 + rg], s_res[bB][rg] + acc + bres[l*128 + rg]);
            }

            // push old res slice into the ring (all reads of this slot happened pre-barrier-1)
            if (tid < 32) {
                int b = tid >> 3, j = tid & 7;
                __stcg(qbase + b*128 + g*8 + j, s_res[b][g*8 + j]);
            }

            grid_sync();   // barrier 2: res fully published

            for (int idx = tid; idx < 512; idx += NT)
                s_res[idx >> 7][idx & 127] = __ldcg(&g_resbuf[idx]);
            // next layer's q0-load __syncthreads orders these writes
        }

        // ---- tail: skip reduce -> fc -> logits -> argmax ----
        __stcg(&g_skipP[(g*4 + my_b    )*128 + my_s], sa0);
        __stcg(&g_skipP[(g*4 + my_b + 2)*128 + my_s], sa1);
        grid_sync();

        if (tid < 32) {   // reduce own 8 skip outputs, relu
            int so = g*8 + (tid >> 2), b = tid & 3;
            float acc = g_bskip[so];
            #pragma unroll
            for (int gg = 0; gg < NB; ++gg)
                acc += __ldcg(&g_skipP[(gg*4 + b)*128 + so]);
            __stcg(&g_relu[b*128 + so], fmaxf(acc, 0.f));
        }
        grid_sync();

        for (int idx = tid; idx < 512; idx += NT)
            s_q0[idx >> 7][idx & 127] = __ldcg(&g_relu[idx]);
        __syncthreads();
        {   // fc (bfc folded into condtop), relu
            const int so = g*8 + rB;
            const float* wf = Wfc + so*128;
            float acc = 0.f;
            #pragma unroll
            for (int i = 0; i < 16; ++i) { int k = t8 + 8*i; acc = fmaf(wf[k], s_q0[bB][k], acc); }
            acc += __shfl_down_sync(0xffffffffu, acc, 4);
            acc += __shfl_down_sync(0xffffffffu, acc, 2);
            acc += __shfl_down_sync(0xffffffffu, acc, 1);
            if (t8 == 0) {
                float v = acc + g_condtop[(e*4 + bB)*128 + so];
                __stcg(&g_sv[bB*128 + so], fmaxf(v, 0.f));
            }
        }
        grid_sync();

        for (int idx = tid; idx < 512; idx += NT)
            s_q0[idx >> 7][idx & 127] = __ldcg(&g_sv[idx]);
        __syncthreads();
        {   // logits: 16 classes per CTA
            const int cls = g*16 + rowA;
            const float* wl = Wlog + cls*128;
            float acc = 0.f;
            #pragma unroll
            for (int i = 0; i < 32; ++i) { int k = t4 + 4*i; acc = fmaf(wl[k], s_q0[bA][k], acc); }
            acc += __shfl_down_sync(0xffffffffu, acc, 2);
            acc += __shfl_down_sync(0xffffffffu, acc, 1);
            if (t4 == 0) {
                float lv = acc + blog[cls];
                out[(bA*256 + cls)*TSTEPS + t] = lv;       // final output
                __stcg(&g_log[bA*256 + cls], lv);
            }
        }
        grid_sync();

        // argmax (first-occurrence semantics, matches jnp.argmax)
        if (g == 0 && tid < 128) {
            int b = tid >> 5, lane = tid & 31;
            float best = -3.4e38f; int bi = 0;
            #pragma unroll
            for (int m = 0; m < 8; ++m) {
                int c = lane*8 + m;
                float v = __ldcg(&g_log[b*256 + c]);
                if (v > best) { best = v; bi = c; }
            }
            #pragma unroll
            for (int off = 16; off > 0; off >>= 1) {
                float ob = __shfl_down_sync(0xffffffffu, best, off);
                int   oi = __shfl_down_sync(0xffffffffu, bi,   off);
                if (ob > best) { best = ob; bi = oi; }   // higher lane = higher idx: strict > keeps first
            }
            if (lane == 0) { int* ps = &g_sample[b]; __stcg(ps, bi); }
        }
        grid_sync();

        if (tid < 4) {
            int smp = __ldcg(&g_sample[tid]);
            s_xp[tid] = s_x[tid];
            s_x[tid]  = (float)smp / 127.5f - 1.0f;
        }
    }
}

// ---------------- launch ----------------
extern "C" void kernel_launch(void* const* d_in, const int* in_sizes, int n_in,
                              void* d_out, int out_size) {
    const float* enc       = (const float*)d_in[0];
    const float* Wf        = (const float*)d_in[1];
    const float* bf        = (const float*)d_in[2];
    const float* Wc        = (const float*)d_in[3];
    const float* bc        = (const float*)d_in[4];
    const float* Wcond     = (const float*)d_in[5];
    const float* Wres      = (const float*)d_in[6];
    const float* bres      = (const float*)d_in[7];
    const float* Wskip_l   = (const float*)d_in[8];
    const float* bskip_l   = (const float*)d_in[9];
    const float* Wskip0    = (const float*)d_in[10];
    const float* bskip0    = (const float*)d_in[11];
    const float* Wcond_top = (const float*)d_in[12];
    const float* Wfc       = (const float*)d_in[13];
    const float* bfc       = (const float*)d_in[14];
    const float* Wlog      = (const float*)d_in[15];
    const float* blog      = (const float*)d_in[16];
    float* out = (float*)d_out;

    prep_condz  <<<256, 256>>>(enc, Wcond, bc);
    prep_condtop<<<8,   256>>>(enc, Wcond_top, bfc);
    prep_bskip  <<<1,   128>>>(bskip0, bskip_l);
    prep_t0     <<<64,  256>>>(Wskip0);
    prep_t1     <<<1024,256>>>(Wskip_l);
    wnet_main   <<<NB,  NT >>>(Wf, bf, Wc, Wres, bres, Wfc, Wlog, blog, out);
}